// round 16
// baseline (speedup 1.0000x reference)
#include <cuda_runtime.h>
#include <cuda_fp16.h>
#include <cstdint>

#define D_DIM 768
#define V_OFF (10240*768)
#define TBM 128
#define TBN 128
#define NKT 48                   // 48 k-chunks of 16
#define RING 8                   // per-warp A ring stages
#define SMEM_DYN (8*RING*1024)   // 8 warps x 8 stages x 1KB

// Fragment-ordered operands:
//  g_Af: A fragments, block (mt, kt) -> 32 lanes x 16B; idx4 = (mt*NKT + kt)*32 + lane
//  g_Bf: B fragments, block (nt, kt) -> same
__device__ uint4 g_Af[1024*NKT*32];
__device__ uint4 g_Bf[48*NKT*32];

__device__ __forceinline__ uint32_t smem_u32(const void* p){
  uint32_t a;
  asm("{ .reg .u64 t; cvta.to.shared.u64 t, %1; cvt.u32.u64 %0, t; }" : "=r"(a) : "l"(p));
  return a;
}
__device__ __forceinline__ void mma16(float* c, const uint4& a, uint32_t b0, uint32_t b1){
  asm volatile(
    "mma.sync.aligned.m16n8k16.row.col.f32.f16.f16.f32 "
    "{%0,%1,%2,%3},{%4,%5,%6,%7},{%8,%9},{%0,%1,%2,%3};\n"
    : "+f"(c[0]), "+f"(c[1]), "+f"(c[2]), "+f"(c[3])
    : "r"(a.x), "r"(a.y), "r"(a.z), "r"(a.w), "r"(b0), "r"(b1));
}
__device__ __forceinline__ void cpasync16(uint32_t dst, const void* src){
  asm volatile("cp.async.cg.shared.global [%0], [%1], 16;"
               :: "r"(dst), "l"(src) : "memory");
}
__device__ __forceinline__ uint4 lds128(uint32_t addr){
  uint4 r;
  asm volatile("ld.shared.v4.b32 {%0,%1,%2,%3}, [%4];"
    : "=r"(r.x), "=r"(r.y), "=r"(r.z), "=r"(r.w) : "r"(addr));
  return r;
}
__device__ __forceinline__ uint32_t pack2(float x, float y){
  __half2 h = __floats2half2_rn(x, y);
  return *reinterpret_cast<uint32_t*>(&h);
}

// ---- prep: build fragment-ordered g_Af (2*pix-1) and g_Bf ----
__global__ void __launch_bounds__(256) prep_frag(const float* __restrict__ pix,
                                                 const float* __restrict__ w){
  const int blk = blockIdx.x;
  const int q = blk*256 + threadIdx.x;
  if (blk < 6144) {
    const int lane = q & 31;
    const int r = q >> 5;
    const int kt = r % NKT, mt = r / NKT;
    const int g  = lane >> 2, t4 = lane & 3;
    const int mA = mt*16 + g;
    const int f0 = kt*16 + 2*t4;
    const int c  = f0 >> 8;
    const int pr = (f0 >> 4) & 15;
    const int fc = f0 & 15;
    const int bA  = mA >> 10,  nA = mA & 1023;
    const int mB_ = mA + 8;
    const int bB  = mB_ >> 10, nB = mB_ & 1023;
    const float* pa = pix + bA*786432 + c*262144 + ((nA >> 5)*16 + pr)*512 + (nA & 31)*16 + fc;
    const float* pb = pix + bB*786432 + c*262144 + ((nB >> 5)*16 + pr)*512 + (nB & 31)*16 + fc;
    float2 a0 = *reinterpret_cast<const float2*>(pa);
    float2 a2 = *reinterpret_cast<const float2*>(pa + 8);
    float2 b0 = *reinterpret_cast<const float2*>(pb);
    float2 b2 = *reinterpret_cast<const float2*>(pb + 8);
    uint4 u;
    u.x = pack2(fmaf(2.f,a0.x,-1.f), fmaf(2.f,a0.y,-1.f));
    u.y = pack2(fmaf(2.f,b0.x,-1.f), fmaf(2.f,b0.y,-1.f));
    u.z = pack2(fmaf(2.f,a2.x,-1.f), fmaf(2.f,a2.y,-1.f));
    u.w = pack2(fmaf(2.f,b2.x,-1.f), fmaf(2.f,b2.y,-1.f));
    g_Af[q] = u;
  } else {
    const int q2 = q - 6144*256;
    const int lane = q2 & 31;
    const int r = q2 >> 5;
    const int kt = r % NKT, nt = r / NKT;
    const int g  = lane >> 2, t4 = lane & 3;
    const int nA = nt*16 + g;
    const int f0 = kt*16 + 2*t4;
    const float* pa = w + nA*D_DIM + f0;
    const float* pb = w + (nA+8)*D_DIM + f0;
    float2 a0 = *reinterpret_cast<const float2*>(pa);
    float2 a2 = *reinterpret_cast<const float2*>(pa + 8);
    float2 b0 = *reinterpret_cast<const float2*>(pb);
    float2 b2 = *reinterpret_cast<const float2*>(pb + 8);
    uint4 u;
    u.x = pack2(a0.x, a0.y);
    u.y = pack2(b0.x, b0.y);
    u.z = pack2(a2.x, a2.y);
    u.w = pack2(b2.x, b2.y);
    g_Bf[q2] = u;
  }
}

// ---- main GEMM: per-warp cp.async ring (depth 8), barrier-free mainloop ----
__global__ void __launch_bounds__(256, 2)
gemma4_patch_embed(const float* __restrict__ ptab,     // (2,10240,768)
                   const int*   __restrict__ pids,     // (16,1024,2)
                   const int*   __restrict__ padp,     // (16,1024) bool-as-i32
                   float* __restrict__ out)            // (16,1024,768)
{
  extern __shared__ char dynsmem[];
  __shared__ int   sO0[TBM];
  __shared__ int   sO1[TBM];
  __shared__ float sPm[TBM];
  const int t  = threadIdx.x;
  const int m0 = blockIdx.y * TBM;
  const int n0 = blockIdx.x * TBN;

  if (t < TBM) {
    const int m = m0 + t;
    int x = pids[2*m];     if (x < 0) x = 0;
    int y = pids[2*m + 1]; if (y < 0) y = 0;
    sO0[t] = x * D_DIM;
    sO1[t] = V_OFF + y * D_DIM;
    sPm[t] = (padp[m] != 0) ? 0.f : 1.f;
  }
  __syncthreads();

  const int warp = t >> 5, lid = t & 31;
  const int wm = (warp >> 1) * 32;        // warp tile 32x64
  const int wn = (warp & 1) * 64;
  const int mt0 = (m0 + wm) >> 4;         // A tiles mt0, mt0+1
  const int nt0 = (n0 + wn) >> 4;         // B tiles nt0..nt0+3

  const uint4* aP0 = g_Af + (size_t)mt0*NKT*32 + lid;
  const uint4* aP1 = aP0 + NKT*32;
  const uint4* bP  = g_Bf + (size_t)nt0*NKT*32 + lid;

  // per-warp private ring: warp*8KB; slot s: +1KB per stage; tile tm: +512B; lane: 16B
  const uint32_t slice = smem_u32(dynsmem) + warp*(RING*1024) + lid*16;

  auto issueA = [&](int s){
    const uint32_t dst = slice + (s & (RING-1))*1024;
    cpasync16(dst,       aP0 + (size_t)s*32);
    cpasync16(dst + 512, aP1 + (size_t)s*32);
  };

  float acc[2][8][4];
  #pragma unroll
  for (int i = 0; i < 2; i++)
    #pragma unroll
    for (int j = 0; j < 8; j++)
      #pragma unroll
      for (int k = 0; k < 4; k++) acc[i][j][k] = 0.f;

  // prologue: fill 7 of 8 ring slots
  #pragma unroll
  for (int p = 0; p < RING-1; p++) {
    issueA(p);
    asm volatile("cp.async.commit_group;" ::: "memory");
  }

  #pragma unroll 2
  for (int kt = 0; kt < NKT; kt++) {
    asm volatile("cp.async.wait_group %0;" :: "n"(RING-2) : "memory");
    const uint32_t slot = slice + (kt & (RING-1))*1024;
    uint4 af0 = lds128(slot);
    uint4 af1 = lds128(slot + 512);

    const int o = kt * 32;
    uint4 bf[4];
    #pragma unroll
    for (int tn = 0; tn < 4; tn++)
      bf[tn] = bP[(size_t)tn*NKT*32 + o];

    issueA((kt + RING-1 < NKT) ? (kt + RING-1) : kt);  // keep group count uniform (re-fetch is harmless)
    asm volatile("cp.async.commit_group;" ::: "memory");

    #pragma unroll
    for (int tn = 0; tn < 4; tn++) {
      mma16(acc[0][2*tn+0], af0, bf[tn].x, bf[tn].z);
      mma16(acc[0][2*tn+1], af0, bf[tn].y, bf[tn].w);
      mma16(acc[1][2*tn+0], af1, bf[tn].x, bf[tn].z);
      mma16(acc[1][2*tn+1], af1, bf[tn].y, bf[tn].w);
    }
  }

  // ---- epilogue ----
  const int g  = lid >> 2, t4 = lid & 3;
  #pragma unroll
  for (int tm = 0; tm < 2; tm++) {
    #pragma unroll
    for (int half = 0; half < 2; half++) {
      const int lrow = wm + tm*16 + g + half*8;
      const int m = m0 + lrow;
      const int o0 = sO0[lrow];
      const int o1 = sO1[lrow];
      const float pm = sPm[lrow];
      float* orow = out + (size_t)m * D_DIM + n0;
      #pragma unroll
      for (int j = 0; j < 8; j++) {
        const int col = wn + j*8 + t4*2;
        const int gc  = n0 + col;
        float2 e0 = *reinterpret_cast<const float2*>(ptab + o0 + gc);
        float2 e1 = *reinterpret_cast<const float2*>(ptab + o1 + gc);
        float2 r;
        r.x = acc[tm][j][half*2 + 0] + pm * (e0.x + e1.x);
        r.y = acc[tm][j][half*2 + 1] + pm * (e0.y + e1.y);
        *reinterpret_cast<float2*>(orow + col) = r;
      }
    }
  }
}

extern "C" void kernel_launch(void* const* d_in, const int* in_sizes, int n_in,
                              void* d_out, int out_size) {
  const float* pix  = (const float*)d_in[0];
  const float* w    = (const float*)d_in[1];
  const float* tab  = (const float*)d_in[2];
  const int*   pids = (const int*)d_in[3];
  const int*   padp = (const int*)d_in[4];
  float* out = (float*)d_out;

  prep_frag<<<6144 + 288, 256>>>(pix, w);

  static int smemSet = 0;
  if (!smemSet) {
    cudaFuncSetAttribute(gemma4_patch_embed,
                         cudaFuncAttributeMaxDynamicSharedMemorySize, SMEM_DYN);
    smemSet = 1;
  }
  dim3 grid(D_DIM / TBN, (16 * 1024) / TBM);   // (6, 128)
  gemma4_patch_embed<<<grid, 256, SMEM_DYN>>>(tab, pids, padp, out);
}

// round 17
// speedup vs baseline: 1.0045x; 1.0045x over previous
#include <cuda_runtime.h>
#include <cuda_fp16.h>
#include <cstdint>

#define D_DIM 768
#define V_OFF (10240*768)
#define TBM 128
#define TBN 128
#define NKT 48                   // 48 k-chunks of 16
#define NIT 24                   // 24 iterations of 2 kt
#define SLOTS 4                  // per-warp ring slots (2 kt each)
#define SLOT_B 2048              // bytes per slot per warp
#define SMEM_DYN (8*SLOTS*SLOT_B)   // 64 KB

// Fragment-ordered operands:
//  g_Af: A fragments, block (mt, kt) -> 32 lanes x 16B; idx4 = (mt*NKT + kt)*32 + lane
//  g_Bf: B fragments, block (nt, kt) -> same
__device__ uint4 g_Af[1024*NKT*32];
__device__ uint4 g_Bf[48*NKT*32];

__device__ __forceinline__ uint32_t smem_u32(const void* p){
  uint32_t a;
  asm("{ .reg .u64 t; cvta.to.shared.u64 t, %1; cvt.u32.u64 %0, t; }" : "=r"(a) : "l"(p));
  return a;
}
__device__ __forceinline__ void mma16(float* c, const uint4& a, uint32_t b0, uint32_t b1){
  asm volatile(
    "mma.sync.aligned.m16n8k16.row.col.f32.f16.f16.f32 "
    "{%0,%1,%2,%3},{%4,%5,%6,%7},{%8,%9},{%0,%1,%2,%3};\n"
    : "+f"(c[0]), "+f"(c[1]), "+f"(c[2]), "+f"(c[3])
    : "r"(a.x), "r"(a.y), "r"(a.z), "r"(a.w), "r"(b0), "r"(b1));
}
__device__ __forceinline__ void cpasync16(uint32_t dst, const void* src){
  asm volatile("cp.async.cg.shared.global [%0], [%1], 16;"
               :: "r"(dst), "l"(src) : "memory");
}
__device__ __forceinline__ uint4 lds128(uint32_t addr){
  uint4 r;
  asm volatile("ld.shared.v4.b32 {%0,%1,%2,%3}, [%4];"
    : "=r"(r.x), "=r"(r.y), "=r"(r.z), "=r"(r.w) : "r"(addr));
  return r;
}
__device__ __forceinline__ uint32_t pack2(float x, float y){
  __half2 h = __floats2half2_rn(x, y);
  return *reinterpret_cast<uint32_t*>(&h);
}

// ---- prep: build fragment-ordered g_Af (2*pix-1) and g_Bf ----
__global__ void __launch_bounds__(256) prep_frag(const float* __restrict__ pix,
                                                 const float* __restrict__ w){
  const int blk = blockIdx.x;
  const int q = blk*256 + threadIdx.x;
  if (blk < 6144) {
    const int lane = q & 31;
    const int r = q >> 5;
    const int kt = r % NKT, mt = r / NKT;
    const int g  = lane >> 2, t4 = lane & 3;
    const int mA = mt*16 + g;
    const int f0 = kt*16 + 2*t4;
    const int c  = f0 >> 8;
    const int pr = (f0 >> 4) & 15;
    const int fc = f0 & 15;
    const int bA  = mA >> 10,  nA = mA & 1023;
    const int mB_ = mA + 8;
    const int bB  = mB_ >> 10, nB = mB_ & 1023;
    const float* pa = pix + bA*786432 + c*262144 + ((nA >> 5)*16 + pr)*512 + (nA & 31)*16 + fc;
    const float* pb = pix + bB*786432 + c*262144 + ((nB >> 5)*16 + pr)*512 + (nB & 31)*16 + fc;
    float2 a0 = *reinterpret_cast<const float2*>(pa);
    float2 a2 = *reinterpret_cast<const float2*>(pa + 8);
    float2 b0 = *reinterpret_cast<const float2*>(pb);
    float2 b2 = *reinterpret_cast<const float2*>(pb + 8);
    uint4 u;
    u.x = pack2(fmaf(2.f,a0.x,-1.f), fmaf(2.f,a0.y,-1.f));
    u.y = pack2(fmaf(2.f,b0.x,-1.f), fmaf(2.f,b0.y,-1.f));
    u.z = pack2(fmaf(2.f,a2.x,-1.f), fmaf(2.f,a2.y,-1.f));
    u.w = pack2(fmaf(2.f,b2.x,-1.f), fmaf(2.f,b2.y,-1.f));
    g_Af[q] = u;
  } else {
    const int q2 = q - 6144*256;
    const int lane = q2 & 31;
    const int r = q2 >> 5;
    const int kt = r % NKT, nt = r / NKT;
    const int g  = lane >> 2, t4 = lane & 3;
    const int nA = nt*16 + g;
    const int f0 = kt*16 + 2*t4;
    const float* pa = w + nA*D_DIM + f0;
    const float* pb = w + (nA+8)*D_DIM + f0;
    float2 a0 = *reinterpret_cast<const float2*>(pa);
    float2 a2 = *reinterpret_cast<const float2*>(pa + 8);
    float2 b0 = *reinterpret_cast<const float2*>(pb);
    float2 b2 = *reinterpret_cast<const float2*>(pb + 8);
    uint4 u;
    u.x = pack2(a0.x, a0.y);
    u.y = pack2(b0.x, b0.y);
    u.z = pack2(a2.x, a2.y);
    u.w = pack2(b2.x, b2.y);
    g_Bf[q2] = u;
  }
}

// ---- main GEMM: per-warp ring of 4 slots x 2kt, barrier-free mainloop ----
__global__ void __launch_bounds__(256, 2)
gemma4_patch_embed(const float* __restrict__ ptab,     // (2,10240,768)
                   const int*   __restrict__ pids,     // (16,1024,2)
                   const int*   __restrict__ padp,     // (16,1024) bool-as-i32
                   float* __restrict__ out)            // (16,1024,768)
{
  extern __shared__ char dynsmem[];
  __shared__ int   sO0[TBM];
  __shared__ int   sO1[TBM];
  __shared__ float sPm[TBM];
  const int t  = threadIdx.x;
  const int m0 = blockIdx.y * TBM;
  const int n0 = blockIdx.x * TBN;

  if (t < TBM) {
    const int m = m0 + t;
    int x = pids[2*m];     if (x < 0) x = 0;
    int y = pids[2*m + 1]; if (y < 0) y = 0;
    sO0[t] = x * D_DIM;
    sO1[t] = V_OFF + y * D_DIM;
    sPm[t] = (padp[m] != 0) ? 0.f : 1.f;
  }
  __syncthreads();

  const int warp = t >> 5, lid = t & 31;
  const int wm = (warp >> 1) * 32;        // warp tile 32x64
  const int wn = (warp & 1) * 64;
  const int mt0 = (m0 + wm) >> 4;         // A tiles mt0, mt0+1
  const int nt0 = (n0 + wn) >> 4;         // B tiles nt0..nt0+3

  const uint4* aP0 = g_Af + (size_t)mt0*NKT*32 + lid;
  const uint4* aP1 = aP0 + NKT*32;
  const uint4* bP  = g_Bf + (size_t)nt0*NKT*32 + lid;

  // per-warp ring: warp*8KB; slot: 2KB; within slot: ktpar*1KB + tile*512B + lane*16B
  const uint32_t slice = smem_u32(dynsmem) + warp*(SLOTS*SLOT_B) + lid*16;

  // issue both kt of one slot (slot index = it & 3), kt0 = 2*it
  auto issueSlot = [&](int it){
    const uint32_t dst = slice + (it & (SLOTS-1))*SLOT_B;
    const size_t o0 = (size_t)(2*it)*32;
    const size_t o1 = o0 + 32;
    cpasync16(dst,            aP0 + o0);
    cpasync16(dst + 512,      aP1 + o0);
    cpasync16(dst + 1024,     aP0 + o1);
    cpasync16(dst + 1536,     aP1 + o1);
  };

  float acc[2][8][4];
  #pragma unroll
  for (int i = 0; i < 2; i++)
    #pragma unroll
    for (int j = 0; j < 8; j++)
      #pragma unroll
      for (int k = 0; k < 4; k++) acc[i][j][k] = 0.f;

  // prologue: fill 3 of 4 slots (prefetch distance 6 kt)
  #pragma unroll
  for (int p = 0; p < SLOTS-1; p++) {
    issueSlot(p);
    asm volatile("cp.async.commit_group;" ::: "memory");
  }

  #pragma unroll 2
  for (int it = 0; it < NIT; it++) {
    asm volatile("cp.async.wait_group %0;" :: "n"(SLOTS-2) : "memory");
    const uint32_t slot = slice + (it & (SLOTS-1))*SLOT_B;

    if (it + SLOTS-1 < NIT) issueSlot(it + SLOTS-1);
    asm volatile("cp.async.commit_group;" ::: "memory");   // empty group in tail is fine

    // --- kt = 2*it ---
    {
      uint4 af0 = lds128(slot);
      uint4 af1 = lds128(slot + 512);
      const size_t o = (size_t)(2*it)*32;
      uint4 bf[4];
      #pragma unroll
      for (int tn = 0; tn < 4; tn++)
        bf[tn] = bP[(size_t)tn*NKT*32 + o];
      #pragma unroll
      for (int tn = 0; tn < 4; tn++) {
        mma16(acc[0][2*tn+0], af0, bf[tn].x, bf[tn].z);
        mma16(acc[0][2*tn+1], af0, bf[tn].y, bf[tn].w);
        mma16(acc[1][2*tn+0], af1, bf[tn].x, bf[tn].z);
        mma16(acc[1][2*tn+1], af1, bf[tn].y, bf[tn].w);
      }
    }
    // --- kt = 2*it + 1 ---
    {
      uint4 af0 = lds128(slot + 1024);
      uint4 af1 = lds128(slot + 1536);
      const size_t o = (size_t)(2*it + 1)*32;
      uint4 bf[4];
      #pragma unroll
      for (int tn = 0; tn < 4; tn++)
        bf[tn] = bP[(size_t)tn*NKT*32 + o];
      #pragma unroll
      for (int tn = 0; tn < 4; tn++) {
        mma16(acc[0][2*tn+0], af0, bf[tn].x, bf[tn].z);
        mma16(acc[0][2*tn+1], af0, bf[tn].y, bf[tn].w);
        mma16(acc[1][2*tn+0], af1, bf[tn].x, bf[tn].z);
        mma16(acc[1][2*tn+1], af1, bf[tn].y, bf[tn].w);
      }
    }
  }

  // ---- epilogue ----
  const int g  = lid >> 2, t4 = lid & 3;
  #pragma unroll
  for (int tm = 0; tm < 2; tm++) {
    #pragma unroll
    for (int half = 0; half < 2; half++) {
      const int lrow = wm + tm*16 + g + half*8;
      const int m = m0 + lrow;
      const int o0 = sO0[lrow];
      const int o1 = sO1[lrow];
      const float pm = sPm[lrow];
      float* orow = out + (size_t)m * D_DIM + n0;
      #pragma unroll
      for (int j = 0; j < 8; j++) {
        const int col = wn + j*8 + t4*2;
        const int gc  = n0 + col;
        float2 e0 = *reinterpret_cast<const float2*>(ptab + o0 + gc);
        float2 e1 = *reinterpret_cast<const float2*>(ptab + o1 + gc);
        float2 r;
        r.x = acc[tm][j][half*2 + 0] + pm * (e0.x + e1.x);
        r.y = acc[tm][j][half*2 + 1] + pm * (e0.y + e1.y);
        *reinterpret_cast<float2*>(orow + col) = r;
      }
    }
  }
}

extern "C" void kernel_launch(void* const* d_in, const int* in_sizes, int n_in,
                              void* d_out, int out_size) {
  const float* pix  = (const float*)d_in[0];
  const float* w    = (const float*)d_in[1];
  const float* tab  = (const float*)d_in[2];
  const int*   pids = (const int*)d_in[3];
  const int*   padp = (const int*)d_in[4];
  float* out = (float*)d_out;

  prep_frag<<<6144 + 288, 256>>>(pix, w);

  static int smemSet = 0;
  if (!smemSet) {
    cudaFuncSetAttribute(gemma4_patch_embed,
                         cudaFuncAttributeMaxDynamicSharedMemorySize, SMEM_DYN);
    smemSet = 1;
  }
  dim3 grid(D_DIM / TBN, (16 * 1024) / TBM);   // (6, 128)
  gemma4_patch_embed<<<grid, 256, SMEM_DYN>>>(tab, pids, padp, out);
}